// round 9
// baseline (speedup 1.0000x reference)
#include <cuda_runtime.h>
#include <cuda_fp16.h>
#include <cuda_bf16.h>
#include <cstdint>

#define DAMPING_PARAM 0.7f
#define N_NODES_C 100000
#define HALF_NODES 50000
#define TPB 1024
#define GRID_CTAS 148

// Per-node accumulator: float4 slot (xyz + pad), 16B aligned.
__device__ float4 g_accum[N_NODES_C];
// Per-node packed table: {q (fp16), pol^(-1/6) (fp16)} -> 4B/node, 400KB total.
__device__ __half2 g_node[N_NODES_C];

__global__ void prep_kernel(const float* __restrict__ charges,
                            const float* __restrict__ pol,
                            int n_nodes) {
    int i = blockIdx.x * blockDim.x + threadIdx.x;
    if (i < n_nodes) {
        g_accum[i] = make_float4(0.f, 0.f, 0.f, 0.f);
        float p = pol[i];
        float ipol = __expf(-__logf(p) * (1.0f / 6.0f));  // p^(-1/6)
        g_node[i] = __floats2half2_rn(charges[i], ipol);
    }
}

// Fetch packed {q,ipol} word for node i from the cluster-distributed smem table.
__device__ __forceinline__ uint32_t table_get(int i) {
    extern __shared__ uint32_t s_tab[];
    uint32_t trank = (uint32_t)(i >= HALF_NODES);
    uint32_t off = (uint32_t)i - trank * HALF_NODES;
    uint32_t local = (uint32_t)__cvta_generic_to_shared(s_tab + off);
    uint32_t remote;
    asm("mapa.shared::cluster.u32 %0, %1, %2;" : "=r"(remote) : "r"(local), "r"(trank));
    uint32_t v;
    asm volatile("ld.shared::cluster.b32 %0, [%1];" : "=r"(v) : "r"(remote));
    return v;
}

__device__ __forceinline__ void edge_accum(int src, int dst, float r,
                                           float vx, float vy, float vz) {
    uint32_t wd = table_get(dst);
    uint32_t ws = table_get(src);
    __half2 hd = *reinterpret_cast<__half2*>(&wd);
    __half2 hs = *reinterpret_cast<__half2*>(&ws);
    float2 nd = __half22float2(hd);                 // .x = q_dst, .y = ipol_dst
    float ipol_s = __half2float(__high2half(hs));

    float u = r * ipol_s * nd.y;                    // r * (pa*pb)^(-1/6)
    float u15 = u * __fsqrt_rn(u);
    float damping = 1.0f - __expf(-DAMPING_PARAM * u15);
    float inv_r = __fdividef(1.0f, r);
    float coeff = -nd.x * damping * inv_r * inv_r * inv_r;

    // One 16B atomic wavefront per edge.
    float4* slot = &g_accum[src];
    asm volatile("red.global.add.v4.f32 [%0], {%1, %2, %3, %4};"
                 :: "l"(slot), "f"(coeff * vx), "f"(coeff * vy),
                    "f"(coeff * vz), "f"(0.0f)
                 : "memory");
}

__global__ __launch_bounds__(TPB, 1) __cluster_dims__(2, 1, 1)
void electric_field_kernel(
    const int* __restrict__ edge_src,
    const int* __restrict__ edge_dst,
    const float* __restrict__ distances,
    const float* __restrict__ vec,
    int n_edges)
{
    extern __shared__ uint32_t s_tab[];  // HALF_NODES words = 200 KB

    uint32_t rank;
    asm("mov.u32 %0, %%cluster_ctarank;" : "=r"(rank));

    // Load this CTA's half of the node table into smem (coalesced).
    const uint32_t* src_tab = reinterpret_cast<const uint32_t*>(g_node) + rank * HALF_NODES;
    for (int i = threadIdx.x; i < HALF_NODES; i += TPB)
        s_tab[i] = __ldg(&src_tab[i]);

    __syncthreads();
    asm volatile("barrier.cluster.arrive.aligned;" ::: "memory");
    asm volatile("barrier.cluster.wait.aligned;" ::: "memory");

    int total_threads = gridDim.x * TPB;
    for (int t = blockIdx.x * TPB + threadIdx.x;; t += total_threads) {
        int e0 = 4 * t;
        if (e0 >= n_edges) break;
        if (e0 + 3 < n_edges) {
            // Streaming loads (evict-first): keep L1 for other data.
            int4   s4 = __ldcs((const int4*)(edge_src) + t);
            int4   d4 = __ldcs((const int4*)(edge_dst) + t);
            float4 r4 = __ldcs((const float4*)(distances) + t);
            const float4* vf4 = (const float4*)vec + 3 * t;
            float4 va = __ldcs(vf4 + 0);  // v0x v0y v0z v1x
            float4 vb = __ldcs(vf4 + 1);  // v1y v1z v2x v2y
            float4 vc = __ldcs(vf4 + 2);  // v2z v3x v3y v3z

            edge_accum(s4.x, d4.x, r4.x, va.x, va.y, va.z);
            edge_accum(s4.y, d4.y, r4.y, va.w, vb.x, vb.y);
            edge_accum(s4.z, d4.z, r4.z, vb.z, vb.w, vc.x);
            edge_accum(s4.w, d4.w, r4.w, vc.y, vc.z, vc.w);
        } else {
            for (int e = e0; e < n_edges; e++) {
                int src = edge_src[e];
                int dst = edge_dst[e];
                float r = distances[e];
                edge_accum(src, dst, r, vec[3 * e], vec[3 * e + 1], vec[3 * e + 2]);
            }
        }
    }

    // No CTA may exit while its peer might still read its smem table.
    asm volatile("barrier.cluster.arrive.aligned;" ::: "memory");
    asm volatile("barrier.cluster.wait.aligned;" ::: "memory");
}

__global__ void compact_kernel(float* __restrict__ out, int n_nodes) {
    int i = blockIdx.x * blockDim.x + threadIdx.x;
    if (i < n_nodes) {
        float4 a = g_accum[i];
        out[3 * i + 0] = a.x;
        out[3 * i + 1] = a.y;
        out[3 * i + 2] = a.z;
    }
}

extern "C" void kernel_launch(void* const* d_in, const int* in_sizes, int n_in,
                              void* d_out, int out_size) {
    // inputs: species[N], edge_src[E], edge_dst[E], distances[E], vec[E*3],
    //         charges[N], polarisability[N]
    const int*   edge_src = (const int*)d_in[1];
    const int*   edge_dst = (const int*)d_in[2];
    const float* dist     = (const float*)d_in[3];
    const float* vec      = (const float*)d_in[4];
    const float* charges  = (const float*)d_in[5];
    const float* pol      = (const float*)d_in[6];
    float* out = (float*)d_out;

    int n_edges = in_sizes[1];
    int n_nodes = in_sizes[0];

    prep_kernel<<<(n_nodes + 255) / 256, 256>>>(charges, pol, n_nodes);

    static int smem_set = 0;
    if (!smem_set) {
        cudaFuncSetAttribute(electric_field_kernel,
                             cudaFuncAttributeMaxDynamicSharedMemorySize,
                             HALF_NODES * 4);
        smem_set = 1;
    }
    electric_field_kernel<<<GRID_CTAS, TPB, HALF_NODES * 4>>>(
        edge_src, edge_dst, dist, vec, n_edges);

    compact_kernel<<<(n_nodes + 255) / 256, 256>>>(out, n_nodes);
}

// round 10
// speedup vs baseline: 1.0443x; 1.0443x over previous
#include <cuda_runtime.h>
#include <cuda_fp16.h>
#include <cuda_bf16.h>
#include <cstdint>

#define DAMPING_PARAM 0.7f
#define N_NODES_C 100000
#define TPB 1024
#define GRID_CTAS 148

// Per-node accumulator: float4 slot (xyz + pad), 16B aligned.
__device__ float4 g_accum[N_NODES_C];
// Per-node fp16 tables (planar): charge and pol^(-1/6).
__device__ __half g_q[N_NODES_C];
__device__ __half g_ipol[N_NODES_C];

__global__ void prep_kernel(const float* __restrict__ charges,
                            const float* __restrict__ pol,
                            int n_nodes) {
    int i = blockIdx.x * blockDim.x + threadIdx.x;
    if (i < n_nodes) {
        g_accum[i] = make_float4(0.f, 0.f, 0.f, 0.f);
        float p = pol[i];
        float ipol = __expf(-__logf(p) * (1.0f / 6.0f));  // p^(-1/6)
        g_q[i] = __float2half_rn(charges[i]);
        g_ipol[i] = __float2half_rn(ipol);
    }
}

extern __shared__ __half s_ipol[];  // full node table: 100000 * 2B = 195.3 KB

__device__ __forceinline__ void edge_accum(int src, int dst, float r,
                                           float vx, float vy, float vz) {
    // Both ipol gathers on the SMEM pipe (cheap), q on L1TEX.
    float ipol_d = __half2float(s_ipol[dst]);
    float ipol_s = __half2float(s_ipol[src]);
    float q      = __half2float(__ldg(&g_q[dst]));

    float u = r * ipol_s * ipol_d;                  // r * (pa*pb)^(-1/6)
    float u15 = u * __fsqrt_rn(u);
    float damping = 1.0f - __expf(-DAMPING_PARAM * u15);
    float inv_r = __fdividef(1.0f, r);
    float coeff = -q * damping * inv_r * inv_r * inv_r;

    // One 16B atomic wavefront per edge.
    float4* slot = &g_accum[src];
    asm volatile("red.global.add.v4.f32 [%0], {%1, %2, %3, %4};"
                 :: "l"(slot), "f"(coeff * vx), "f"(coeff * vy),
                    "f"(coeff * vz), "f"(0.0f)
                 : "memory");
}

__global__ __launch_bounds__(TPB, 1)
void electric_field_kernel(
    const int* __restrict__ edge_src,
    const int* __restrict__ edge_dst,
    const float* __restrict__ distances,
    const float* __restrict__ vec,
    int n_edges)
{
    // Load the full ipol table into smem (coalesced 4B words).
    const uint32_t* tab32 = reinterpret_cast<const uint32_t*>(g_ipol);
    uint32_t* s32 = reinterpret_cast<uint32_t*>(s_ipol);
    #pragma unroll 4
    for (int i = threadIdx.x; i < N_NODES_C / 2; i += TPB)
        s32[i] = __ldg(&tab32[i]);
    __syncthreads();

    int total_threads = gridDim.x * TPB;
    for (int t = blockIdx.x * TPB + threadIdx.x;; t += total_threads) {
        int e0 = 4 * t;
        if (e0 >= n_edges) break;
        if (e0 + 3 < n_edges) {
            // Streaming loads (evict-first).
            int4   s4 = __ldcs((const int4*)(edge_src) + t);
            int4   d4 = __ldcs((const int4*)(edge_dst) + t);
            float4 r4 = __ldcs((const float4*)(distances) + t);
            const float4* vf4 = (const float4*)vec + 3 * t;
            float4 va = __ldcs(vf4 + 0);  // v0x v0y v0z v1x
            float4 vb = __ldcs(vf4 + 1);  // v1y v1z v2x v2y
            float4 vc = __ldcs(vf4 + 2);  // v2z v3x v3y v3z

            edge_accum(s4.x, d4.x, r4.x, va.x, va.y, va.z);
            edge_accum(s4.y, d4.y, r4.y, va.w, vb.x, vb.y);
            edge_accum(s4.z, d4.z, r4.z, vb.z, vb.w, vc.x);
            edge_accum(s4.w, d4.w, r4.w, vc.y, vc.z, vc.w);
        } else {
            for (int e = e0; e < n_edges; e++) {
                int src = edge_src[e];
                int dst = edge_dst[e];
                float r = distances[e];
                edge_accum(src, dst, r, vec[3 * e], vec[3 * e + 1], vec[3 * e + 2]);
            }
        }
    }
}

__global__ void compact_kernel(float* __restrict__ out, int n_nodes) {
    int i = blockIdx.x * blockDim.x + threadIdx.x;
    if (i < n_nodes) {
        float4 a = g_accum[i];
        out[3 * i + 0] = a.x;
        out[3 * i + 1] = a.y;
        out[3 * i + 2] = a.z;
    }
}

extern "C" void kernel_launch(void* const* d_in, const int* in_sizes, int n_in,
                              void* d_out, int out_size) {
    // inputs: species[N], edge_src[E], edge_dst[E], distances[E], vec[E*3],
    //         charges[N], polarisability[N]
    const int*   edge_src = (const int*)d_in[1];
    const int*   edge_dst = (const int*)d_in[2];
    const float* dist     = (const float*)d_in[3];
    const float* vec      = (const float*)d_in[4];
    const float* charges  = (const float*)d_in[5];
    const float* pol      = (const float*)d_in[6];
    float* out = (float*)d_out;

    int n_edges = in_sizes[1];
    int n_nodes = in_sizes[0];

    const int smem_bytes = N_NODES_C * 2;  // 200000 B

    static int smem_set = 0;
    if (!smem_set) {
        cudaFuncSetAttribute(electric_field_kernel,
                             cudaFuncAttributeMaxDynamicSharedMemorySize,
                             smem_bytes);
        smem_set = 1;
    }

    prep_kernel<<<(n_nodes + 255) / 256, 256>>>(charges, pol, n_nodes);

    electric_field_kernel<<<GRID_CTAS, TPB, smem_bytes>>>(
        edge_src, edge_dst, dist, vec, n_edges);

    compact_kernel<<<(n_nodes + 255) / 256, 256>>>(out, n_nodes);
}

// round 11
// speedup vs baseline: 1.3735x; 1.3153x over previous
#include <cuda_runtime.h>
#include <cuda_fp16.h>
#include <cuda_bf16.h>
#include <cstdint>

#define DAMPING_PARAM 0.7f
#define N_NODES_MAX 100000

// Per-node accumulator: float4 slot (xyz + pad), 16B aligned.
__device__ float4 g_accum[N_NODES_MAX];
// Per-node packed table: {q (fp16), pol^(-1/6) (fp16)} -> 4B/node, 400KB total.
__device__ __half2 g_node[N_NODES_MAX];

__global__ void prep_kernel(const float* __restrict__ charges,
                            const float* __restrict__ pol,
                            int n_nodes) {
    int i = blockIdx.x * blockDim.x + threadIdx.x;
    if (i < n_nodes) {
        g_accum[i] = make_float4(0.f, 0.f, 0.f, 0.f);
        float p = pol[i];
        float ipol = __expf(-__logf(p) * (1.0f / 6.0f));  // p^(-1/6)
        g_node[i] = __floats2half2_rn(charges[i], ipol);
    }
}

// Table gathers with L1 evict-last priority: keep the node table resident in L1
// while the edge streams (loaded with __ldcs, evict-first) pass through.
__device__ __forceinline__ uint32_t ldg_el_b32(const void* p) {
    uint32_t v;
    asm volatile("ld.global.nc.L1::evict_last.b32 %0, [%1];" : "=r"(v) : "l"(p));
    return v;
}
__device__ __forceinline__ uint16_t ldg_el_u16(const void* p) {
    uint16_t v;
    asm volatile("ld.global.nc.L1::evict_last.u16 %0, [%1];" : "=h"(v) : "l"(p));
    return v;
}

__device__ __forceinline__ void edge_accum(int src, int dst, float r,
                                           float vx, float vy, float vz) {
    uint32_t wd = ldg_el_b32(&g_node[dst]);          // {q, ipol_dst}, 4B gather
    uint16_t ws = ldg_el_u16((const __half*)&g_node[src] + 1);  // ipol_src, 2B

    __half2 hd = *reinterpret_cast<__half2*>(&wd);
    float2 nd = __half22float2(hd);                  // .x = q, .y = ipol_dst
    __half hs = *reinterpret_cast<__half*>(&ws);
    float ipol_s = __half2float(hs);

    float u = r * ipol_s * nd.y;                     // r * (pa*pb)^(-1/6)
    float u15 = u * __fsqrt_rn(u);
    float damping = 1.0f - __expf(-DAMPING_PARAM * u15);
    float inv_r = __fdividef(1.0f, r);
    float coeff = -nd.x * damping * inv_r * inv_r * inv_r;

    // One 16B atomic wavefront per edge.
    float4* slot = &g_accum[src];
    asm volatile("red.global.add.v4.f32 [%0], {%1, %2, %3, %4};"
                 :: "l"(slot), "f"(coeff * vx), "f"(coeff * vy),
                    "f"(coeff * vz), "f"(0.0f)
                 : "memory");
}

__global__ __launch_bounds__(256) void electric_field_kernel(
    const int* __restrict__ edge_src,
    const int* __restrict__ edge_dst,
    const float* __restrict__ distances,
    const float* __restrict__ vec,
    int n_edges)
{
    int t = blockIdx.x * blockDim.x + threadIdx.x;
    int e0 = 4 * t;
    if (e0 + 3 < n_edges) {
        // Streaming loads (evict-first) so the gather table stays in L1.
        int4   s4 = __ldcs((const int4*)(edge_src) + t);
        int4   d4 = __ldcs((const int4*)(edge_dst) + t);
        float4 r4 = __ldcs((const float4*)(distances) + t);
        const float4* vf4 = (const float4*)vec + 3 * t;
        float4 va = __ldcs(vf4 + 0);  // v0x v0y v0z v1x
        float4 vb = __ldcs(vf4 + 1);  // v1y v1z v2x v2y
        float4 vc = __ldcs(vf4 + 2);  // v2z v3x v3y v3z

        edge_accum(s4.x, d4.x, r4.x, va.x, va.y, va.z);
        edge_accum(s4.y, d4.y, r4.y, va.w, vb.x, vb.y);
        edge_accum(s4.z, d4.z, r4.z, vb.z, vb.w, vc.x);
        edge_accum(s4.w, d4.w, r4.w, vc.y, vc.z, vc.w);
    } else {
        for (int e = e0; e < n_edges; e++) {
            int src = edge_src[e];
            int dst = edge_dst[e];
            float r = distances[e];
            edge_accum(src, dst, r, vec[3 * e], vec[3 * e + 1], vec[3 * e + 2]);
        }
    }
}

__global__ void compact_kernel(float* __restrict__ out, int n_nodes) {
    int i = blockIdx.x * blockDim.x + threadIdx.x;
    if (i < n_nodes) {
        float4 a = g_accum[i];
        out[3 * i + 0] = a.x;
        out[3 * i + 1] = a.y;
        out[3 * i + 2] = a.z;
    }
}

extern "C" void kernel_launch(void* const* d_in, const int* in_sizes, int n_in,
                              void* d_out, int out_size) {
    // inputs: species[N], edge_src[E], edge_dst[E], distances[E], vec[E*3],
    //         charges[N], polarisability[N]
    const int*   edge_src = (const int*)d_in[1];
    const int*   edge_dst = (const int*)d_in[2];
    const float* dist     = (const float*)d_in[3];
    const float* vec      = (const float*)d_in[4];
    const float* charges  = (const float*)d_in[5];
    const float* pol      = (const float*)d_in[6];
    float* out = (float*)d_out;

    int n_edges = in_sizes[1];
    int n_nodes = in_sizes[0];

    prep_kernel<<<(n_nodes + 255) / 256, 256>>>(charges, pol, n_nodes);

    int n_threads = (n_edges + 3) / 4;
    electric_field_kernel<<<(n_threads + 255) / 256, 256>>>(
        edge_src, edge_dst, dist, vec, n_edges);

    compact_kernel<<<(n_nodes + 255) / 256, 256>>>(out, n_nodes);
}